// round 3
// baseline (speedup 1.0000x reference)
#include <cuda_runtime.h>
#include <math.h>

// Problem constants
#define BB 4
#define NC 6
#define BN 24          // BB*NC
#define CC 80
#define DD 112
#define HH 16
#define WW 44
#define KK 264         // NC*WW
#define XY 16384
#define OC1 64

typedef unsigned long long u64;

// ---- packed f32x2 helpers (Blackwell FFMA2 path, PTX-only) ----
__device__ __forceinline__ u64 fma2(u64 a, u64 b, u64 c) {
    u64 d;
    asm("fma.rn.f32x2 %0, %1, %2, %3;" : "=l"(d) : "l"(a), "l"(b), "l"(c));
    return d;
}
__device__ __forceinline__ u64 mul2(u64 a, u64 b) {
    u64 d;
    asm("mul.rn.f32x2 %0, %1, %2;" : "=l"(d) : "l"(a), "l"(b));
    return d;
}
__device__ __forceinline__ u64 pkdup(float v) {
    u64 r;
    asm("mov.b64 %0, {%1, %2};" : "=l"(r) : "f"(v), "f"(v));
    return r;
}
__device__ __forceinline__ float2 up2(u64 v) {
    float2 f;
    asm("mov.b64 {%0, %1}, %2;" : "=f"(f.x), "=f"(f.y) : "l"(v));
    return f;
}

// Scratch (device globals; no allocation allowed)
__device__ float g_h1[BN * OC1 * HH * WW];   // conv1+relu output
__device__ float g_vw[BN * HH * WW];         // vertical softmax weights
__device__ float g_m[BN * HH * WW];          // depth softmax max
__device__ float g_inv[BN * HH * WW];        // vw / sumexp
__device__ float g_dpt[BB * KK * DD];        // depth_prime transposed [b][k][d]
__device__ float g_fpt[BB * KK * CC];        // feat_prime transposed [b][k][c]

// ---------------------------------------------------------------------------
// K1: conv1 (80->64, 3x3 SAME) + bias + relu -> g_h1, f32x2 over ic-pairs
// grid (16 y, 24 bn), block 256: thread = (oc in [0,64), xq in [0,4)) -> 11 x
// ---------------------------------------------------------------------------
__global__ __launch_bounds__(256) void k1_conv1(const float* __restrict__ feature,
                                                const float* __restrict__ w1,
                                                const float* __restrict__ b1) {
    int y = blockIdx.x, bn = blockIdx.y;
    int t = threadIdx.x;
    int oc = t & 63, xq = t >> 6;

    __shared__ float2 plane2[3][WW];     // rows (y-1,y,y+1), ic pair packed
    __shared__ float2 wsm2[OC1][9];

    u64 acc[11];
#pragma unroll
    for (int i = 0; i < 11; i++) acc[i] = 0ull;
    float bias = b1[oc];

    for (int ic = 0; ic < CC; ic += 2) {
        __syncthreads();
        if (t < 3 * WW) {
            int r = t / WW, xx = t % WW;
            int yy = y - 1 + r;
            float v0 = 0.f, v1 = 0.f;
            if (yy >= 0 && yy < HH) {
                v0 = feature[((bn * CC + ic) * HH + yy) * WW + xx];
                v1 = feature[((bn * CC + ic + 1) * HH + yy) * WW + xx];
            }
            plane2[r][xx] = make_float2(v0, v1);
        }
        for (int p = t; p < OC1 * 9; p += 256) {
            int o = p / 9, q = p % 9;
            wsm2[o][q] = make_float2(w1[o * (CC * 9) + ic * 9 + q],
                                     w1[o * (CC * 9) + (ic + 1) * 9 + q]);
        }
        __syncthreads();

        u64 w9[9];
#pragma unroll
        for (int q = 0; q < 9; q++) w9[q] = *(const u64*)&wsm2[oc][q];

        int xb = xq * 11;
        u64 A0 = 0, A1 = 0, A2 = 0, B0, B1, B2;
        if (xb - 1 >= 0) {
            A0 = *(const u64*)&plane2[0][xb - 1];
            A1 = *(const u64*)&plane2[1][xb - 1];
            A2 = *(const u64*)&plane2[2][xb - 1];
        }
        B0 = *(const u64*)&plane2[0][xb];
        B1 = *(const u64*)&plane2[1][xb];
        B2 = *(const u64*)&plane2[2][xb];
#pragma unroll
        for (int i = 0; i < 11; i++) {
            int xn = xb + i + 1;
            u64 C0 = 0, C1 = 0, C2 = 0;
            if (xn < WW) {
                C0 = *(const u64*)&plane2[0][xn];
                C1 = *(const u64*)&plane2[1][xn];
                C2 = *(const u64*)&plane2[2][xn];
            }
            u64 a = acc[i];
            a = fma2(w9[0], A0, a); a = fma2(w9[3], A1, a); a = fma2(w9[6], A2, a);
            a = fma2(w9[1], B0, a); a = fma2(w9[4], B1, a); a = fma2(w9[7], B2, a);
            a = fma2(w9[2], C0, a); a = fma2(w9[5], C1, a); a = fma2(w9[8], C2, a);
            acc[i] = a;
            A0 = B0; A1 = B1; A2 = B2;
            B0 = C0; B1 = C1; B2 = C2;
        }
    }
#pragma unroll
    for (int i = 0; i < 11; i++) {
        float2 f = up2(acc[i]);
        float v = f.x + f.y + bias;
        g_h1[((bn * OC1 + oc) * HH + y) * WW + xq * 11 + i] = v > 0.f ? v : 0.f;
    }
}

// ---------------------------------------------------------------------------
// K2: conv2 (64->1, 3x3 SAME) + bias, then softmax over H -> g_vw
// ---------------------------------------------------------------------------
__global__ __launch_bounds__(704) void k2_vertw(const float* __restrict__ w2,
                                                const float* __restrict__ b2) {
    int bn = blockIdx.x;
    int t = threadIdx.x;
    int h = t / WW, w = t % WW;

    __shared__ float plane[HH * WW];
    __shared__ float w2s[9];
    __shared__ float ss[HH * WW];

    float acc = 0.f;
    for (int ic = 0; ic < OC1; ic++) {
        __syncthreads();
        plane[t] = g_h1[(bn * OC1 + ic) * (HH * WW) + t];
        if (t < 9) w2s[t] = w2[ic * 9 + t];
        __syncthreads();
#pragma unroll
        for (int r = 0; r < 3; r++) {
            int yy = h - 1 + r;
            if (yy < 0 || yy >= HH) continue;
#pragma unroll
            for (int dx = 0; dx < 3; dx++) {
                int xx = w - 1 + dx;
                if (xx < 0 || xx >= WW) continue;
                acc += w2s[r * 3 + dx] * plane[yy * WW + xx];
            }
        }
    }
    float s = acc + b2[0];
    ss[t] = s;
    __syncthreads();
    float m = -1e30f;
#pragma unroll
    for (int hh = 0; hh < HH; hh++) m = fmaxf(m, ss[hh * WW + w]);
    float denom = 0.f;
#pragma unroll
    for (int hh = 0; hh < HH; hh++) denom += __expf(ss[hh * WW + w] - m);
    g_vw[bn * (HH * WW) + t] = __expf(s - m) / denom;
}

// ---------------------------------------------------------------------------
// K3a: depth softmax stats per (bn,h,w): max over D and vw/sumexp
// ---------------------------------------------------------------------------
__global__ __launch_bounds__(352) void k3a_stats(const float* __restrict__ logits) {
    int h = blockIdx.x, bn = blockIdx.y;
    int t = threadIdx.x;
    int w = t % WW, g = t / WW;

    int base = bn * (DD * HH * WW) + h * WW + w;

    __shared__ float red[8][WW];
    __shared__ float red2[8][WW];

    float m = -1e30f;
    for (int d = g; d < DD; d += 8) m = fmaxf(m, logits[base + d * (HH * WW)]);
    red[g][w] = m;
    __syncthreads();
    if (g == 0) {
        float mm = red[0][w];
#pragma unroll
        for (int j = 1; j < 8; j++) mm = fmaxf(mm, red[j][w]);
        red[0][w] = mm;
    }
    __syncthreads();
    m = red[0][w];

    float s = 0.f;
    for (int d = g; d < DD; d += 8) s += __expf(logits[base + d * (HH * WW)] - m);
    red2[g][w] = s;
    __syncthreads();
    if (g == 0) {
        float sum = 0.f;
#pragma unroll
        for (int j = 0; j < 8; j++) sum += red2[j][w];
        int idx = bn * (HH * WW) + h * WW + w;
        g_m[idx] = m;
        g_inv[idx] = g_vw[idx] / sum;
    }
}

// ---------------------------------------------------------------------------
// K3b: depth_prime[b][k][d] = sum_h exp(l-m)*inv
// ---------------------------------------------------------------------------
__global__ __launch_bounds__(704) void k3b_reduce(const float* __restrict__ logits) {
    int dc = blockIdx.x, bn = blockIdx.y;
    int t = threadIdx.x;
    int h = t / WW, w = t % WW;

    int idx = bn * (HH * WW) + t;
    float m = g_m[idx], inv = g_inv[idx];
    int base = bn * (DD * HH * WW) + t;

    __shared__ float red[8][HH][WW + 1];
    float v[8];
#pragma unroll
    for (int dd = 0; dd < 8; dd++)
        v[dd] = __expf(logits[base + (dc * 8 + dd) * (HH * WW)] - m) * inv;
#pragma unroll
    for (int dd = 0; dd < 8; dd++) red[dd][h][w] = v[dd];
    __syncthreads();

    if (t < 8 * WW) {
        int dd = t / WW, ww = t % WW;
        float s = 0.f;
#pragma unroll
        for (int hh = 0; hh < HH; hh++) s += red[dd][hh][ww];
        int b = bn / NC, n = bn % NC;
        g_dpt[(b * KK + n * WW + ww) * DD + dc * 8 + dd] = s;
    }
}

// ---------------------------------------------------------------------------
// K4: feat_prime[b][k][c] = max_h feature
// ---------------------------------------------------------------------------
__global__ __launch_bounds__(256) void k4_featmax(const float* __restrict__ feature) {
    int bn = blockIdx.x;
    int b = bn / NC, n = bn % NC;
    for (int p = threadIdx.x; p < CC * WW; p += 256) {
        int c = p / WW, w = p % WW;
        const float* f = feature + ((bn * CC + c) * HH) * WW + w;
        float m = f[0];
#pragma unroll
        for (int h = 1; h < HH; h++) m = fmaxf(m, f[h * WW]);
        g_fpt[(b * KK + n * WW + w) * CC + c] = m;
    }
}

// ---------------------------------------------------------------------------
// K5: fused BEV projection with packed f32x2 FMA.
// out[b,c,v] = sum_k fp[b,k,c] * ray[b,k,v] * (sum_d dp[b,k,d]*circle[b,d,v])
// grid (128 vtile, 4 b), block 256, ~109 KB dynamic smem, 2 blocks/SM.
// ---------------------------------------------------------------------------
#define TV 128
#define KC 24
#define SM_CIRCLE   (DD * TV)          // 14336 floats
#define SM_DP2      (KC * 113 * 2)     // 5424  (duplicated f32x2 pairs)
#define SM_RAY      (KC * TV)          // 3072
#define SM_FP       (KC * 81)          // 1944
#define SM_PR       (KC * 132)         // 3168
#define SM_TOTAL_FL (SM_CIRCLE + SM_DP2 + SM_RAY + SM_FP + SM_PR)  // 27944
#define SM_TOTAL_BYTES (SM_TOTAL_FL * 4)                           // 111776

__global__ __launch_bounds__(256, 2) void k5_bev(const float* __restrict__ circle,
                                                 const float* __restrict__ ray,
                                                 float* __restrict__ out) {
    extern __shared__ float smem[];
    float* circle_s = smem;
    float* dp2_s    = circle_s + SM_CIRCLE;   // float2-duplicated dp
    float* ray_s    = dp2_s + SM_DP2;
    float* fp_s     = ray_s + SM_RAY;
    float* pr_s     = fp_s + SM_FP;

    int b  = blockIdx.y;
    int v0 = blockIdx.x * TV;
    int t  = threadIdx.x;

    // Load circle tile [112][128] (float4)
    for (int p = t; p < DD * (TV / 4); p += 256) {
        int d = p >> 5, c4 = p & 31;
        ((float4*)(circle_s + d * TV))[c4] =
            ((const float4*)(circle + (size_t)(b * DD + d) * XY + v0))[c4];
    }

    u64 oacc[5][4];
#pragma unroll
    for (int j = 0; j < 5; j++)
#pragma unroll
        for (int i = 0; i < 4; i++) oacc[j][i] = 0ull;

    int kth  = t & 7,  vth  = t >> 3;   // phase 1: 8 k-threads x 32 v-threads
    int cth  = t >> 4, vth2 = t & 15;   // phase 2: 16 c-threads x 16 v-threads

    for (int kc = 0; kc < KK / KC; kc++) {
        int k0 = kc * KC;
        __syncthreads();   // pr_s of previous chunk fully consumed

        // ---- tile loads ----
        for (int p = t; p < KC * DD; p += 256) {
            int kk = p / DD, d = p - kk * DD;
            float v = g_dpt[(b * KK + k0 + kk) * DD + d];
            ((float2*)dp2_s)[kk * 113 + d] = make_float2(v, v);
        }
        for (int p = t; p < KC * (TV / 4); p += 256) {
            int kk = p >> 5, c4 = p & 31;
            ((float4*)(ray_s + kk * TV))[c4] =
                ((const float4*)(ray + (size_t)(b * KK + k0 + kk) * XY + v0))[c4];
        }
        for (int p = t; p < KC * CC; p += 256) {
            int kk = p / CC, c = p % CC;
            fp_s[kk * 81 + c] = g_fpt[(b * KK + k0 + kk) * CC + c];
        }
        __syncthreads();

        // ---- phase 1: pr[kk][tv] = (dp[kk,:] . circle[:,tv]) * ray[kk][tv] ----
        {
            u64 a00 = 0, a01 = 0, a10 = 0, a11 = 0, a20 = 0, a21 = 0;
            const u64* dpp = (const u64*)dp2_s + kth * 3 * 113;
            const float* cp = circle_s + vth * 4;
#pragma unroll 4
            for (int d = 0; d < DD; d++) {
                u64 c01 = *(const u64*)(cp + d * TV);
                u64 c23 = *(const u64*)(cp + d * TV + 2);
                u64 A0 = dpp[d], A1 = dpp[113 + d], A2 = dpp[226 + d];
                a00 = fma2(A0, c01, a00); a01 = fma2(A0, c23, a01);
                a10 = fma2(A1, c01, a10); a11 = fma2(A1, c23, a11);
                a20 = fma2(A2, c01, a20); a21 = fma2(A2, c23, a21);
            }
            int kk0 = kth * 3;
            u64 r0a = *(const u64*)(ray_s + kk0 * TV + vth * 4);
            u64 r0b = *(const u64*)(ray_s + kk0 * TV + vth * 4 + 2);
            *(u64*)(pr_s + kk0 * 132 + vth * 4)     = mul2(a00, r0a);
            *(u64*)(pr_s + kk0 * 132 + vth * 4 + 2) = mul2(a01, r0b);
            u64 r1a = *(const u64*)(ray_s + (kk0 + 1) * TV + vth * 4);
            u64 r1b = *(const u64*)(ray_s + (kk0 + 1) * TV + vth * 4 + 2);
            *(u64*)(pr_s + (kk0 + 1) * 132 + vth * 4)     = mul2(a10, r1a);
            *(u64*)(pr_s + (kk0 + 1) * 132 + vth * 4 + 2) = mul2(a11, r1b);
            u64 r2a = *(const u64*)(ray_s + (kk0 + 2) * TV + vth * 4);
            u64 r2b = *(const u64*)(ray_s + (kk0 + 2) * TV + vth * 4 + 2);
            *(u64*)(pr_s + (kk0 + 2) * 132 + vth * 4)     = mul2(a20, r2a);
            *(u64*)(pr_s + (kk0 + 2) * 132 + vth * 4 + 2) = mul2(a21, r2b);
        }
        __syncthreads();

        // ---- phase 2: out[c][v] += fp[kk][c] * pr[kk][v]  (bank-conflict-free) ----
#pragma unroll 6
        for (int kk = 0; kk < KC; kk++) {
            const u64* prp = (const u64*)(pr_s + kk * 132);
            u64 p0 = prp[vth2];
            u64 p1 = prp[vth2 + 16];
            u64 p2 = prp[vth2 + 32];
            u64 p3 = prp[vth2 + 48];
            const float* fp = fp_s + kk * 81 + cth * 5;
#pragma unroll
            for (int j = 0; j < 5; j++) {
                u64 F = pkdup(fp[j]);
                oacc[j][0] = fma2(F, p0, oacc[j][0]);
                oacc[j][1] = fma2(F, p1, oacc[j][1]);
                oacc[j][2] = fma2(F, p2, oacc[j][2]);
                oacc[j][3] = fma2(F, p3, oacc[j][3]);
            }
        }
    }

    // ---- epilogue: out[b, c, v] ----
#pragma unroll
    for (int j = 0; j < 5; j++) {
        float* op = out + (size_t)(b * CC + cth * 5 + j) * XY + v0;
#pragma unroll
        for (int i = 0; i < 4; i++) {
            float2 f = up2(oacc[j][i]);
            *(float2*)(op + (vth2 + 16 * i) * 2) = f;
        }
    }
}

// ---------------------------------------------------------------------------
extern "C" void kernel_launch(void* const* d_in, const int* in_sizes, int n_in,
                              void* d_out, int out_size) {
    const float* feature = (const float*)d_in[0];
    const float* logits  = (const float*)d_in[1];
    const float* circle  = (const float*)d_in[2];
    const float* ray     = (const float*)d_in[3];
    const float* w1      = (const float*)d_in[4];
    const float* b1      = (const float*)d_in[5];
    const float* w2      = (const float*)d_in[6];
    const float* b2      = (const float*)d_in[7];
    float* out = (float*)d_out;

    k1_conv1<<<dim3(HH, BN), 256>>>(feature, w1, b1);
    k2_vertw<<<BN, HH * WW>>>(w2, b2);
    k3a_stats<<<dim3(HH, BN), 8 * WW>>>(logits);
    k3b_reduce<<<dim3(DD / 8, BN), HH * WW>>>(logits);
    k4_featmax<<<BN, 256>>>(feature);

    cudaFuncSetAttribute(k5_bev, cudaFuncAttributeMaxDynamicSharedMemorySize,
                         SM_TOTAL_BYTES);
    k5_bev<<<dim3(XY / TV, BB), 256, SM_TOTAL_BYTES>>>(circle, ray, out);
}

// round 4
// speedup vs baseline: 1.0092x; 1.0092x over previous
#include <cuda_runtime.h>
#include <math.h>

// Problem constants
#define BB 4
#define NC 6
#define BN 24          // BB*NC
#define CC 80
#define DD 112
#define HH 16
#define WW 44
#define KK 264         // NC*WW
#define XY 16384
#define OC1 64

typedef unsigned long long u64;

// ---- packed f32x2 helpers (Blackwell FFMA2 path, PTX-only) ----
__device__ __forceinline__ u64 fma2(u64 a, u64 b, u64 c) {
    u64 d;
    asm("fma.rn.f32x2 %0, %1, %2, %3;" : "=l"(d) : "l"(a), "l"(b), "l"(c));
    return d;
}
__device__ __forceinline__ u64 mul2(u64 a, u64 b) {
    u64 d;
    asm("mul.rn.f32x2 %0, %1, %2;" : "=l"(d) : "l"(a), "l"(b));
    return d;
}
__device__ __forceinline__ u64 pkdup(float v) {
    u64 r;
    asm("mov.b64 %0, {%1, %2};" : "=l"(r) : "f"(v), "f"(v));
    return r;
}
__device__ __forceinline__ float2 up2(u64 v) {
    float2 f;
    asm("mov.b64 {%0, %1}, %2;" : "=f"(f.x), "=f"(f.y) : "l"(v));
    return f;
}

// Scratch (device globals; no allocation allowed)
__device__ float g_h1[BN * OC1 * HH * WW];   // conv1+relu output
__device__ float g_vw[BN * HH * WW];         // vertical softmax weights
__device__ float g_m[BN * HH * WW];          // depth softmax max
__device__ float g_inv[BN * HH * WW];        // vw / sumexp
__device__ float g_dpt[BB * KK * DD];        // depth_prime transposed [b][k][d]
__device__ float g_fpt[BB * KK * CC];        // feat_prime transposed [b][k][c]

// ---------------------------------------------------------------------------
// K1: conv1 (80->64, 3x3 SAME) + bias + relu -> g_h1, f32x2 over ic-pairs
// grid (16 y, 24 bn), block 256: thread = (oc in [0,64), xq in [0,4)) -> 11 x
// ---------------------------------------------------------------------------
__global__ __launch_bounds__(256) void k1_conv1(const float* __restrict__ feature,
                                                const float* __restrict__ w1,
                                                const float* __restrict__ b1) {
    int y = blockIdx.x, bn = blockIdx.y;
    int t = threadIdx.x;
    int oc = t & 63, xq = t >> 6;

    __shared__ float2 plane2[3][WW];     // rows (y-1,y,y+1), ic pair packed
    __shared__ float2 wsm2[OC1][9];

    u64 acc[11];
#pragma unroll
    for (int i = 0; i < 11; i++) acc[i] = 0ull;
    float bias = b1[oc];

    for (int ic = 0; ic < CC; ic += 2) {
        __syncthreads();
        if (t < 3 * WW) {
            int r = t / WW, xx = t % WW;
            int yy = y - 1 + r;
            float v0 = 0.f, v1 = 0.f;
            if (yy >= 0 && yy < HH) {
                v0 = feature[((bn * CC + ic) * HH + yy) * WW + xx];
                v1 = feature[((bn * CC + ic + 1) * HH + yy) * WW + xx];
            }
            plane2[r][xx] = make_float2(v0, v1);
        }
        for (int p = t; p < OC1 * 9; p += 256) {
            int o = p / 9, q = p % 9;
            wsm2[o][q] = make_float2(w1[o * (CC * 9) + ic * 9 + q],
                                     w1[o * (CC * 9) + (ic + 1) * 9 + q]);
        }
        __syncthreads();

        u64 w9[9];
#pragma unroll
        for (int q = 0; q < 9; q++) w9[q] = *(const u64*)&wsm2[oc][q];

        int xb = xq * 11;
        u64 A0 = 0, A1 = 0, A2 = 0, B0, B1, B2;
        if (xb - 1 >= 0) {
            A0 = *(const u64*)&plane2[0][xb - 1];
            A1 = *(const u64*)&plane2[1][xb - 1];
            A2 = *(const u64*)&plane2[2][xb - 1];
        }
        B0 = *(const u64*)&plane2[0][xb];
        B1 = *(const u64*)&plane2[1][xb];
        B2 = *(const u64*)&plane2[2][xb];
#pragma unroll
        for (int i = 0; i < 11; i++) {
            int xn = xb + i + 1;
            u64 C0 = 0, C1 = 0, C2 = 0;
            if (xn < WW) {
                C0 = *(const u64*)&plane2[0][xn];
                C1 = *(const u64*)&plane2[1][xn];
                C2 = *(const u64*)&plane2[2][xn];
            }
            u64 a = acc[i];
            a = fma2(w9[0], A0, a); a = fma2(w9[3], A1, a); a = fma2(w9[6], A2, a);
            a = fma2(w9[1], B0, a); a = fma2(w9[4], B1, a); a = fma2(w9[7], B2, a);
            a = fma2(w9[2], C0, a); a = fma2(w9[5], C1, a); a = fma2(w9[8], C2, a);
            acc[i] = a;
            A0 = B0; A1 = B1; A2 = B2;
            B0 = C0; B1 = C1; B2 = C2;
        }
    }
#pragma unroll
    for (int i = 0; i < 11; i++) {
        float2 f = up2(acc[i]);
        float v = f.x + f.y + bias;
        g_h1[((bn * OC1 + oc) * HH + y) * WW + xq * 11 + i] = v > 0.f ? v : 0.f;
    }
}

// ---------------------------------------------------------------------------
// K2: conv2 (64->1, 3x3 SAME) + bias, then softmax over H -> g_vw
// ---------------------------------------------------------------------------
__global__ __launch_bounds__(704) void k2_vertw(const float* __restrict__ w2,
                                                const float* __restrict__ b2) {
    int bn = blockIdx.x;
    int t = threadIdx.x;
    int h = t / WW, w = t % WW;

    __shared__ float plane[HH * WW];
    __shared__ float w2s[9];
    __shared__ float ss[HH * WW];

    float acc = 0.f;
    for (int ic = 0; ic < OC1; ic++) {
        __syncthreads();
        plane[t] = g_h1[(bn * OC1 + ic) * (HH * WW) + t];
        if (t < 9) w2s[t] = w2[ic * 9 + t];
        __syncthreads();
#pragma unroll
        for (int r = 0; r < 3; r++) {
            int yy = h - 1 + r;
            if (yy < 0 || yy >= HH) continue;
#pragma unroll
            for (int dx = 0; dx < 3; dx++) {
                int xx = w - 1 + dx;
                if (xx < 0 || xx >= WW) continue;
                acc += w2s[r * 3 + dx] * plane[yy * WW + xx];
            }
        }
    }
    float s = acc + b2[0];
    ss[t] = s;
    __syncthreads();
    float m = -1e30f;
#pragma unroll
    for (int hh = 0; hh < HH; hh++) m = fmaxf(m, ss[hh * WW + w]);
    float denom = 0.f;
#pragma unroll
    for (int hh = 0; hh < HH; hh++) denom += __expf(ss[hh * WW + w] - m);
    g_vw[bn * (HH * WW) + t] = __expf(s - m) / denom;
}

// ---------------------------------------------------------------------------
// K3a: depth softmax stats per (bn,h,w): max over D and vw/sumexp
// ---------------------------------------------------------------------------
__global__ __launch_bounds__(352) void k3a_stats(const float* __restrict__ logits) {
    int h = blockIdx.x, bn = blockIdx.y;
    int t = threadIdx.x;
    int w = t % WW, g = t / WW;

    int base = bn * (DD * HH * WW) + h * WW + w;

    __shared__ float red[8][WW];
    __shared__ float red2[8][WW];

    float m = -1e30f;
    for (int d = g; d < DD; d += 8) m = fmaxf(m, logits[base + d * (HH * WW)]);
    red[g][w] = m;
    __syncthreads();
    if (g == 0) {
        float mm = red[0][w];
#pragma unroll
        for (int j = 1; j < 8; j++) mm = fmaxf(mm, red[j][w]);
        red[0][w] = mm;
    }
    __syncthreads();
    m = red[0][w];

    float s = 0.f;
    for (int d = g; d < DD; d += 8) s += __expf(logits[base + d * (HH * WW)] - m);
    red2[g][w] = s;
    __syncthreads();
    if (g == 0) {
        float sum = 0.f;
#pragma unroll
        for (int j = 0; j < 8; j++) sum += red2[j][w];
        int idx = bn * (HH * WW) + h * WW + w;
        g_m[idx] = m;
        g_inv[idx] = g_vw[idx] / sum;
    }
}

// ---------------------------------------------------------------------------
// K3b: depth_prime[b][k][d] = sum_h exp(l-m)*inv
// ---------------------------------------------------------------------------
__global__ __launch_bounds__(704) void k3b_reduce(const float* __restrict__ logits) {
    int dc = blockIdx.x, bn = blockIdx.y;
    int t = threadIdx.x;
    int h = t / WW, w = t % WW;

    int idx = bn * (HH * WW) + t;
    float m = g_m[idx], inv = g_inv[idx];
    int base = bn * (DD * HH * WW) + t;

    __shared__ float red[8][HH][WW + 1];
    float v[8];
#pragma unroll
    for (int dd = 0; dd < 8; dd++)
        v[dd] = __expf(logits[base + (dc * 8 + dd) * (HH * WW)] - m) * inv;
#pragma unroll
    for (int dd = 0; dd < 8; dd++) red[dd][h][w] = v[dd];
    __syncthreads();

    if (t < 8 * WW) {
        int dd = t / WW, ww = t % WW;
        float s = 0.f;
#pragma unroll
        for (int hh = 0; hh < HH; hh++) s += red[dd][hh][ww];
        int b = bn / NC, n = bn % NC;
        g_dpt[(b * KK + n * WW + ww) * DD + dc * 8 + dd] = s;
    }
}

// ---------------------------------------------------------------------------
// K4: feat_prime[b][k][c] = max_h feature
// ---------------------------------------------------------------------------
__global__ __launch_bounds__(256) void k4_featmax(const float* __restrict__ feature) {
    int bn = blockIdx.x;
    int b = bn / NC, n = bn % NC;
    for (int p = threadIdx.x; p < CC * WW; p += 256) {
        int c = p / WW, w = p % WW;
        const float* f = feature + ((bn * CC + c) * HH) * WW + w;
        float m = f[0];
#pragma unroll
        for (int h = 1; h < HH; h++) m = fmaxf(m, f[h * WW]);
        g_fpt[(b * KK + n * WW + w) * CC + c] = m;
    }
}

// ---------------------------------------------------------------------------
// K5: fused BEV projection with packed f32x2 FMA.
// out[b,c,v] = sum_k fp[b,k,c] * ray[b,k,v] * (sum_d dp[b,k,d]*circle[b,d,v])
// grid (128 vtile, 4 b), block 256, ~109 KB dynamic smem, 2 blocks/SM.
// ---------------------------------------------------------------------------
#define TV 128
#define KC 24
#define SM_CIRCLE   (DD * TV)          // 14336 floats
#define SM_DP2      (KC * 113 * 2)     // 5424  (duplicated f32x2 pairs)
#define SM_RAY      (KC * TV)          // 3072
#define SM_FP       (KC * 81)          // 1944
#define SM_PR       (KC * 132)         // 3168
#define SM_TOTAL_FL (SM_CIRCLE + SM_DP2 + SM_RAY + SM_FP + SM_PR)  // 27944
#define SM_TOTAL_BYTES (SM_TOTAL_FL * 4)                           // 111776

__global__ __launch_bounds__(256, 2) void k5_bev(const float* __restrict__ circle,
                                                 const float* __restrict__ ray,
                                                 float* __restrict__ out) {
    extern __shared__ float smem[];
    float* circle_s = smem;
    float* dp2_s    = circle_s + SM_CIRCLE;   // float2-duplicated dp
    float* ray_s    = dp2_s + SM_DP2;
    float* fp_s     = ray_s + SM_RAY;
    float* pr_s     = fp_s + SM_FP;

    int b  = blockIdx.y;
    int v0 = blockIdx.x * TV;
    int t  = threadIdx.x;

    // Load circle tile [112][128] (float4)
    for (int p = t; p < DD * (TV / 4); p += 256) {
        int d = p >> 5, c4 = p & 31;
        ((float4*)(circle_s + d * TV))[c4] =
            ((const float4*)(circle + (size_t)(b * DD + d) * XY + v0))[c4];
    }

    u64 oacc[5][4];
#pragma unroll
    for (int j = 0; j < 5; j++)
#pragma unroll
        for (int i = 0; i < 4; i++) oacc[j][i] = 0ull;

    int kth  = t & 7,  vth  = t >> 3;   // phase 1: 8 k-threads x 32 v-threads
    int cth  = t >> 4, vth2 = t & 15;   // phase 2: 16 c-threads x 16 v-threads

    for (int kc = 0; kc < KK / KC; kc++) {
        int k0 = kc * KC;
        __syncthreads();   // pr_s of previous chunk fully consumed

        // ---- tile loads ----
        for (int p = t; p < KC * DD; p += 256) {
            int kk = p / DD, d = p - kk * DD;
            float v = g_dpt[(b * KK + k0 + kk) * DD + d];
            ((float2*)dp2_s)[kk * 113 + d] = make_float2(v, v);
        }
        for (int p = t; p < KC * (TV / 4); p += 256) {
            int kk = p >> 5, c4 = p & 31;
            ((float4*)(ray_s + kk * TV))[c4] =
                ((const float4*)(ray + (size_t)(b * KK + k0 + kk) * XY + v0))[c4];
        }
        for (int p = t; p < KC * CC; p += 256) {
            int kk = p / CC, c = p % CC;
            fp_s[kk * 81 + c] = g_fpt[(b * KK + k0 + kk) * CC + c];
        }
        __syncthreads();

        // ---- phase 1: pr[kk][tv] = (dp[kk,:] . circle[:,tv]) * ray[kk][tv] ----
        {
            u64 a00 = 0, a01 = 0, a10 = 0, a11 = 0, a20 = 0, a21 = 0;
            const u64* dpp = (const u64*)dp2_s + kth * 3 * 113;
            const float* cp = circle_s + vth * 4;
#pragma unroll 4
            for (int d = 0; d < DD; d++) {
                u64 c01 = *(const u64*)(cp + d * TV);
                u64 c23 = *(const u64*)(cp + d * TV + 2);
                u64 A0 = dpp[d], A1 = dpp[113 + d], A2 = dpp[226 + d];
                a00 = fma2(A0, c01, a00); a01 = fma2(A0, c23, a01);
                a10 = fma2(A1, c01, a10); a11 = fma2(A1, c23, a11);
                a20 = fma2(A2, c01, a20); a21 = fma2(A2, c23, a21);
            }
            int kk0 = kth * 3;
            u64 r0a = *(const u64*)(ray_s + kk0 * TV + vth * 4);
            u64 r0b = *(const u64*)(ray_s + kk0 * TV + vth * 4 + 2);
            *(u64*)(pr_s + kk0 * 132 + vth * 4)     = mul2(a00, r0a);
            *(u64*)(pr_s + kk0 * 132 + vth * 4 + 2) = mul2(a01, r0b);
            u64 r1a = *(const u64*)(ray_s + (kk0 + 1) * TV + vth * 4);
            u64 r1b = *(const u64*)(ray_s + (kk0 + 1) * TV + vth * 4 + 2);
            *(u64*)(pr_s + (kk0 + 1) * 132 + vth * 4)     = mul2(a10, r1a);
            *(u64*)(pr_s + (kk0 + 1) * 132 + vth * 4 + 2) = mul2(a11, r1b);
            u64 r2a = *(const u64*)(ray_s + (kk0 + 2) * TV + vth * 4);
            u64 r2b = *(const u64*)(ray_s + (kk0 + 2) * TV + vth * 4 + 2);
            *(u64*)(pr_s + (kk0 + 2) * 132 + vth * 4)     = mul2(a20, r2a);
            *(u64*)(pr_s + (kk0 + 2) * 132 + vth * 4 + 2) = mul2(a21, r2b);
        }
        __syncthreads();

        // ---- phase 2: out[c][v] += fp[kk][c] * pr[kk][v]  (bank-conflict-free) ----
#pragma unroll 6
        for (int kk = 0; kk < KC; kk++) {
            const u64* prp = (const u64*)(pr_s + kk * 132);
            u64 p0 = prp[vth2];
            u64 p1 = prp[vth2 + 16];
            u64 p2 = prp[vth2 + 32];
            u64 p3 = prp[vth2 + 48];
            const float* fp = fp_s + kk * 81 + cth * 5;
#pragma unroll
            for (int j = 0; j < 5; j++) {
                u64 F = pkdup(fp[j]);
                oacc[j][0] = fma2(F, p0, oacc[j][0]);
                oacc[j][1] = fma2(F, p1, oacc[j][1]);
                oacc[j][2] = fma2(F, p2, oacc[j][2]);
                oacc[j][3] = fma2(F, p3, oacc[j][3]);
            }
        }
    }

    // ---- epilogue: out[b, c, v] ----
#pragma unroll
    for (int j = 0; j < 5; j++) {
        float* op = out + (size_t)(b * CC + cth * 5 + j) * XY + v0;
#pragma unroll
        for (int i = 0; i < 4; i++) {
            float2 f = up2(oacc[j][i]);
            *(float2*)(op + (vth2 + 16 * i) * 2) = f;
        }
    }
}

// ---------------------------------------------------------------------------
extern "C" void kernel_launch(void* const* d_in, const int* in_sizes, int n_in,
                              void* d_out, int out_size) {
    const float* feature = (const float*)d_in[0];
    const float* logits  = (const float*)d_in[1];
    const float* circle  = (const float*)d_in[2];
    const float* ray     = (const float*)d_in[3];
    const float* w1      = (const float*)d_in[4];
    const float* b1      = (const float*)d_in[5];
    const float* w2      = (const float*)d_in[6];
    const float* b2      = (const float*)d_in[7];
    float* out = (float*)d_out;

    k1_conv1<<<dim3(HH, BN), 256>>>(feature, w1, b1);
    k2_vertw<<<BN, HH * WW>>>(w2, b2);
    k3a_stats<<<dim3(HH, BN), 8 * WW>>>(logits);
    k3b_reduce<<<dim3(DD / 8, BN), HH * WW>>>(logits);
    k4_featmax<<<BN, 256>>>(feature);

    cudaFuncSetAttribute(k5_bev, cudaFuncAttributeMaxDynamicSharedMemorySize,
                         SM_TOTAL_BYTES);
    k5_bev<<<dim3(XY / TV, BB), 256, SM_TOTAL_BYTES>>>(circle, ray, out);
}

// round 5
// speedup vs baseline: 1.0126x; 1.0034x over previous
#include <cuda_runtime.h>
#include <math.h>

// Problem constants
#define BB 4
#define NC 6
#define BN 24          // BB*NC
#define CC 80
#define DD 112
#define HH 16
#define WW 44
#define KK 264         // NC*WW
#define XY 16384
#define OC1 64

typedef unsigned long long u64;

// ---- packed f32x2 helpers (Blackwell FFMA2 path, PTX-only) ----
__device__ __forceinline__ u64 fma2(u64 a, u64 b, u64 c) {
    u64 d;
    asm("fma.rn.f32x2 %0, %1, %2, %3;" : "=l"(d) : "l"(a), "l"(b), "l"(c));
    return d;
}
__device__ __forceinline__ u64 mul2(u64 a, u64 b) {
    u64 d;
    asm("mul.rn.f32x2 %0, %1, %2;" : "=l"(d) : "l"(a), "l"(b));
    return d;
}
__device__ __forceinline__ u64 pkdup(float v) {
    u64 r;
    asm("mov.b64 %0, {%1, %2};" : "=l"(r) : "f"(v), "f"(v));
    return r;
}
__device__ __forceinline__ float2 up2(u64 v) {
    float2 f;
    asm("mov.b64 {%0, %1}, %2;" : "=f"(f.x), "=f"(f.y) : "l"(v));
    return f;
}

// Scratch (device globals; no allocation allowed)
__device__ float g_h1[BN * OC1 * HH * WW];   // conv1+relu output
__device__ float g_vw[BN * HH * WW];         // vertical softmax weights
__device__ float g_m[BN * HH * WW];          // depth softmax max
__device__ float g_inv[BN * HH * WW];        // vw / sumexp
__device__ float g_dpt[BB * KK * DD];        // depth_prime transposed [b][k][d]
__device__ float g_fpt[BB * KK * CC];        // feat_prime transposed [b][k][c]

// ---------------------------------------------------------------------------
// K1: conv1 (80->64, 3x3 SAME) + bias + relu -> g_h1, f32x2 over ic-pairs
// grid (16 y, 24 bn), block 256: thread = (oc in [0,64), xq in [0,4)) -> 11 x
// ---------------------------------------------------------------------------
__global__ __launch_bounds__(256) void k1_conv1(const float* __restrict__ feature,
                                                const float* __restrict__ w1,
                                                const float* __restrict__ b1) {
    int y = blockIdx.x, bn = blockIdx.y;
    int t = threadIdx.x;
    int oc = t & 63, xq = t >> 6;

    __shared__ float2 plane2[3][WW];     // rows (y-1,y,y+1), ic pair packed
    __shared__ float2 wsm2[OC1][9];

    u64 acc[11];
#pragma unroll
    for (int i = 0; i < 11; i++) acc[i] = 0ull;
    float bias = b1[oc];

    for (int ic = 0; ic < CC; ic += 2) {
        __syncthreads();
        if (t < 3 * WW) {
            int r = t / WW, xx = t % WW;
            int yy = y - 1 + r;
            float v0 = 0.f, v1 = 0.f;
            if (yy >= 0 && yy < HH) {
                v0 = feature[((bn * CC + ic) * HH + yy) * WW + xx];
                v1 = feature[((bn * CC + ic + 1) * HH + yy) * WW + xx];
            }
            plane2[r][xx] = make_float2(v0, v1);
        }
        for (int p = t; p < OC1 * 9; p += 256) {
            int o = p / 9, q = p % 9;
            wsm2[o][q] = make_float2(w1[o * (CC * 9) + ic * 9 + q],
                                     w1[o * (CC * 9) + (ic + 1) * 9 + q]);
        }
        __syncthreads();

        u64 w9[9];
#pragma unroll
        for (int q = 0; q < 9; q++) w9[q] = *(const u64*)&wsm2[oc][q];

        int xb = xq * 11;
        u64 A0 = 0, A1 = 0, A2 = 0, B0, B1, B2;
        if (xb - 1 >= 0) {
            A0 = *(const u64*)&plane2[0][xb - 1];
            A1 = *(const u64*)&plane2[1][xb - 1];
            A2 = *(const u64*)&plane2[2][xb - 1];
        }
        B0 = *(const u64*)&plane2[0][xb];
        B1 = *(const u64*)&plane2[1][xb];
        B2 = *(const u64*)&plane2[2][xb];
#pragma unroll
        for (int i = 0; i < 11; i++) {
            int xn = xb + i + 1;
            u64 C0 = 0, C1 = 0, C2 = 0;
            if (xn < WW) {
                C0 = *(const u64*)&plane2[0][xn];
                C1 = *(const u64*)&plane2[1][xn];
                C2 = *(const u64*)&plane2[2][xn];
            }
            u64 a = acc[i];
            a = fma2(w9[0], A0, a); a = fma2(w9[3], A1, a); a = fma2(w9[6], A2, a);
            a = fma2(w9[1], B0, a); a = fma2(w9[4], B1, a); a = fma2(w9[7], B2, a);
            a = fma2(w9[2], C0, a); a = fma2(w9[5], C1, a); a = fma2(w9[8], C2, a);
            acc[i] = a;
            A0 = B0; A1 = B1; A2 = B2;
            B0 = C0; B1 = C1; B2 = C2;
        }
    }
#pragma unroll
    for (int i = 0; i < 11; i++) {
        float2 f = up2(acc[i]);
        float v = f.x + f.y + bias;
        g_h1[((bn * OC1 + oc) * HH + y) * WW + xq * 11 + i] = v > 0.f ? v : 0.f;
    }
}

// ---------------------------------------------------------------------------
// K2: conv2 (64->1, 3x3 SAME) + bias, then softmax over H -> g_vw
// ---------------------------------------------------------------------------
__global__ __launch_bounds__(704) void k2_vertw(const float* __restrict__ w2,
                                                const float* __restrict__ b2) {
    int bn = blockIdx.x;
    int t = threadIdx.x;
    int h = t / WW, w = t % WW;

    __shared__ float plane[HH * WW];
    __shared__ float w2s[9];
    __shared__ float ss[HH * WW];

    float acc = 0.f;
    for (int ic = 0; ic < OC1; ic++) {
        __syncthreads();
        plane[t] = g_h1[(bn * OC1 + ic) * (HH * WW) + t];
        if (t < 9) w2s[t] = w2[ic * 9 + t];
        __syncthreads();
#pragma unroll
        for (int r = 0; r < 3; r++) {
            int yy = h - 1 + r;
            if (yy < 0 || yy >= HH) continue;
#pragma unroll
            for (int dx = 0; dx < 3; dx++) {
                int xx = w - 1 + dx;
                if (xx < 0 || xx >= WW) continue;
                acc += w2s[r * 3 + dx] * plane[yy * WW + xx];
            }
        }
    }
    float s = acc + b2[0];
    ss[t] = s;
    __syncthreads();
    float m = -1e30f;
#pragma unroll
    for (int hh = 0; hh < HH; hh++) m = fmaxf(m, ss[hh * WW + w]);
    float denom = 0.f;
#pragma unroll
    for (int hh = 0; hh < HH; hh++) denom += __expf(ss[hh * WW + w] - m);
    g_vw[bn * (HH * WW) + t] = __expf(s - m) / denom;
}

// ---------------------------------------------------------------------------
// K3a: depth softmax stats per (bn,h,w): max over D and vw/sumexp
// ---------------------------------------------------------------------------
__global__ __launch_bounds__(352) void k3a_stats(const float* __restrict__ logits) {
    int h = blockIdx.x, bn = blockIdx.y;
    int t = threadIdx.x;
    int w = t % WW, g = t / WW;

    int base = bn * (DD * HH * WW) + h * WW + w;

    __shared__ float red[8][WW];
    __shared__ float red2[8][WW];

    float m = -1e30f;
    for (int d = g; d < DD; d += 8) m = fmaxf(m, logits[base + d * (HH * WW)]);
    red[g][w] = m;
    __syncthreads();
    if (g == 0) {
        float mm = red[0][w];
#pragma unroll
        for (int j = 1; j < 8; j++) mm = fmaxf(mm, red[j][w]);
        red[0][w] = mm;
    }
    __syncthreads();
    m = red[0][w];

    float s = 0.f;
    for (int d = g; d < DD; d += 8) s += __expf(logits[base + d * (HH * WW)] - m);
    red2[g][w] = s;
    __syncthreads();
    if (g == 0) {
        float sum = 0.f;
#pragma unroll
        for (int j = 0; j < 8; j++) sum += red2[j][w];
        int idx = bn * (HH * WW) + h * WW + w;
        g_m[idx] = m;
        g_inv[idx] = g_vw[idx] / sum;
    }
}

// ---------------------------------------------------------------------------
// K3b: depth_prime[b][k][d] = sum_h exp(l-m)*inv
// ---------------------------------------------------------------------------
__global__ __launch_bounds__(704) void k3b_reduce(const float* __restrict__ logits) {
    int dc = blockIdx.x, bn = blockIdx.y;
    int t = threadIdx.x;
    int h = t / WW, w = t % WW;

    int idx = bn * (HH * WW) + t;
    float m = g_m[idx], inv = g_inv[idx];
    int base = bn * (DD * HH * WW) + t;

    __shared__ float red[8][HH][WW + 1];
    float v[8];
#pragma unroll
    for (int dd = 0; dd < 8; dd++)
        v[dd] = __expf(logits[base + (dc * 8 + dd) * (HH * WW)] - m) * inv;
#pragma unroll
    for (int dd = 0; dd < 8; dd++) red[dd][h][w] = v[dd];
    __syncthreads();

    if (t < 8 * WW) {
        int dd = t / WW, ww = t % WW;
        float s = 0.f;
#pragma unroll
        for (int hh = 0; hh < HH; hh++) s += red[dd][hh][ww];
        int b = bn / NC, n = bn % NC;
        g_dpt[(b * KK + n * WW + ww) * DD + dc * 8 + dd] = s;
    }
}

// ---------------------------------------------------------------------------
// K4: feat_prime[b][k][c] = max_h feature
// ---------------------------------------------------------------------------
__global__ __launch_bounds__(256) void k4_featmax(const float* __restrict__ feature) {
    int bn = blockIdx.x;
    int b = bn / NC, n = bn % NC;
    for (int p = threadIdx.x; p < CC * WW; p += 256) {
        int c = p / WW, w = p % WW;
        const float* f = feature + ((bn * CC + c) * HH) * WW + w;
        float m = f[0];
#pragma unroll
        for (int h = 1; h < HH; h++) m = fmaxf(m, f[h * WW]);
        g_fpt[(b * KK + n * WW + w) * CC + c] = m;
    }
}

// ---------------------------------------------------------------------------
// K5: fused BEV projection with packed f32x2 FMA.
// out[b,c,v] = sum_k fp[b,k,c] * ray[b,k,v] * (sum_d dp[b,k,d]*circle[b,d,v])
// grid (128 vtile, 4 b), block 256, ~109 KB dynamic smem, 2 blocks/SM.
// ---------------------------------------------------------------------------
#define TV 128
#define KC 24
#define SM_CIRCLE   (DD * TV)          // 14336 floats
#define SM_DP2      (KC * 113 * 2)     // 5424  (duplicated f32x2 pairs)
#define SM_RAY      (KC * TV)          // 3072
#define SM_FP       (KC * 81)          // 1944
#define SM_PR       (KC * 132)         // 3168
#define SM_TOTAL_FL (SM_CIRCLE + SM_DP2 + SM_RAY + SM_FP + SM_PR)  // 27944
#define SM_TOTAL_BYTES (SM_TOTAL_FL * 4)                           // 111776

__global__ __launch_bounds__(256, 2) void k5_bev(const float* __restrict__ circle,
                                                 const float* __restrict__ ray,
                                                 float* __restrict__ out) {
    extern __shared__ float smem[];
    float* circle_s = smem;
    float* dp2_s    = circle_s + SM_CIRCLE;   // float2-duplicated dp
    float* ray_s    = dp2_s + SM_DP2;
    float* fp_s     = ray_s + SM_RAY;
    float* pr_s     = fp_s + SM_FP;

    int b  = blockIdx.y;
    int v0 = blockIdx.x * TV;
    int t  = threadIdx.x;

    // Load circle tile [112][128] (float4)
    for (int p = t; p < DD * (TV / 4); p += 256) {
        int d = p >> 5, c4 = p & 31;
        ((float4*)(circle_s + d * TV))[c4] =
            ((const float4*)(circle + (size_t)(b * DD + d) * XY + v0))[c4];
    }

    u64 oacc[5][4];
#pragma unroll
    for (int j = 0; j < 5; j++)
#pragma unroll
        for (int i = 0; i < 4; i++) oacc[j][i] = 0ull;

    int kth  = t & 7,  vth  = t >> 3;   // phase 1: 8 k-threads x 32 v-threads
    int cth  = t >> 4, vth2 = t & 15;   // phase 2: 16 c-threads x 16 v-threads

    for (int kc = 0; kc < KK / KC; kc++) {
        int k0 = kc * KC;
        __syncthreads();   // pr_s of previous chunk fully consumed

        // ---- tile loads ----
        for (int p = t; p < KC * DD; p += 256) {
            int kk = p / DD, d = p - kk * DD;
            float v = g_dpt[(b * KK + k0 + kk) * DD + d];
            ((float2*)dp2_s)[kk * 113 + d] = make_float2(v, v);
        }
        for (int p = t; p < KC * (TV / 4); p += 256) {
            int kk = p >> 5, c4 = p & 31;
            ((float4*)(ray_s + kk * TV))[c4] =
                ((const float4*)(ray + (size_t)(b * KK + k0 + kk) * XY + v0))[c4];
        }
        for (int p = t; p < KC * CC; p += 256) {
            int kk = p / CC, c = p % CC;
            fp_s[kk * 81 + c] = g_fpt[(b * KK + k0 + kk) * CC + c];
        }
        __syncthreads();

        // ---- phase 1: pr[kk][tv] = (dp[kk,:] . circle[:,tv]) * ray[kk][tv] ----
        {
            u64 a00 = 0, a01 = 0, a10 = 0, a11 = 0, a20 = 0, a21 = 0;
            const u64* dpp = (const u64*)dp2_s + kth * 3 * 113;
            const float* cp = circle_s + vth * 4;
#pragma unroll 4
            for (int d = 0; d < DD; d++) {
                u64 c01 = *(const u64*)(cp + d * TV);
                u64 c23 = *(const u64*)(cp + d * TV + 2);
                u64 A0 = dpp[d], A1 = dpp[113 + d], A2 = dpp[226 + d];
                a00 = fma2(A0, c01, a00); a01 = fma2(A0, c23, a01);
                a10 = fma2(A1, c01, a10); a11 = fma2(A1, c23, a11);
                a20 = fma2(A2, c01, a20); a21 = fma2(A2, c23, a21);
            }
            int kk0 = kth * 3;
            u64 r0a = *(const u64*)(ray_s + kk0 * TV + vth * 4);
            u64 r0b = *(const u64*)(ray_s + kk0 * TV + vth * 4 + 2);
            *(u64*)(pr_s + kk0 * 132 + vth * 4)     = mul2(a00, r0a);
            *(u64*)(pr_s + kk0 * 132 + vth * 4 + 2) = mul2(a01, r0b);
            u64 r1a = *(const u64*)(ray_s + (kk0 + 1) * TV + vth * 4);
            u64 r1b = *(const u64*)(ray_s + (kk0 + 1) * TV + vth * 4 + 2);
            *(u64*)(pr_s + (kk0 + 1) * 132 + vth * 4)     = mul2(a10, r1a);
            *(u64*)(pr_s + (kk0 + 1) * 132 + vth * 4 + 2) = mul2(a11, r1b);
            u64 r2a = *(const u64*)(ray_s + (kk0 + 2) * TV + vth * 4);
            u64 r2b = *(const u64*)(ray_s + (kk0 + 2) * TV + vth * 4 + 2);
            *(u64*)(pr_s + (kk0 + 2) * 132 + vth * 4)     = mul2(a20, r2a);
            *(u64*)(pr_s + (kk0 + 2) * 132 + vth * 4 + 2) = mul2(a21, r2b);
        }
        __syncthreads();

        // ---- phase 2: out[c][v] += fp[kk][c] * pr[kk][v]  (bank-conflict-free) ----
#pragma unroll 6
        for (int kk = 0; kk < KC; kk++) {
            const u64* prp = (const u64*)(pr_s + kk * 132);
            u64 p0 = prp[vth2];
            u64 p1 = prp[vth2 + 16];
            u64 p2 = prp[vth2 + 32];
            u64 p3 = prp[vth2 + 48];
            const float* fp = fp_s + kk * 81 + cth * 5;
#pragma unroll
            for (int j = 0; j < 5; j++) {
                u64 F = pkdup(fp[j]);
                oacc[j][0] = fma2(F, p0, oacc[j][0]);
                oacc[j][1] = fma2(F, p1, oacc[j][1]);
                oacc[j][2] = fma2(F, p2, oacc[j][2]);
                oacc[j][3] = fma2(F, p3, oacc[j][3]);
            }
        }
    }

    // ---- epilogue: out[b, c, v] ----
#pragma unroll
    for (int j = 0; j < 5; j++) {
        float* op = out + (size_t)(b * CC + cth * 5 + j) * XY + v0;
#pragma unroll
        for (int i = 0; i < 4; i++) {
            float2 f = up2(oacc[j][i]);
            *(float2*)(op + (vth2 + 16 * i) * 2) = f;
        }
    }
}

// ---------------------------------------------------------------------------
extern "C" void kernel_launch(void* const* d_in, const int* in_sizes, int n_in,
                              void* d_out, int out_size) {
    const float* feature = (const float*)d_in[0];
    const float* logits  = (const float*)d_in[1];
    const float* circle  = (const float*)d_in[2];
    const float* ray     = (const float*)d_in[3];
    const float* w1      = (const float*)d_in[4];
    const float* b1      = (const float*)d_in[5];
    const float* w2      = (const float*)d_in[6];
    const float* b2      = (const float*)d_in[7];
    float* out = (float*)d_out;

    k1_conv1<<<dim3(HH, BN), 256>>>(feature, w1, b1);
    k2_vertw<<<BN, HH * WW>>>(w2, b2);
    k3a_stats<<<dim3(HH, BN), 8 * WW>>>(logits);
    k3b_reduce<<<dim3(DD / 8, BN), HH * WW>>>(logits);
    k4_featmax<<<BN, 256>>>(feature);

    cudaFuncSetAttribute(k5_bev, cudaFuncAttributeMaxDynamicSharedMemorySize,
                         SM_TOTAL_BYTES);
    k5_bev<<<dim3(XY / TV, BB), 256, SM_TOTAL_BYTES>>>(circle, ray, out);
}